// round 4
// baseline (speedup 1.0000x reference)
#include <cuda_runtime.h>
#include <cstdint>

#define N_NODES 50000
#define N_EDGES 800000
#define N_FEATS 64
#define NQUADS  (N_EDGES / 4)
#define SRC_BYTES (N_NODES * 4)        // 200000 B, multiple of 16
#define SMEM_TOTAL (16 + SRC_BYTES)    // mbar (16B slot) + staged src

// Scratch (allocation-free)
__device__ float g_deg[N_NODES];
__device__ float g_a[N_NODES];
__device__ float g_b[N_NODES];
__device__ float g_c[N_NODES];
__device__ unsigned g_packed[N_EDGES];   // (row << 16) | col

__device__ __forceinline__ uint32_t smem_u32(const void* p) {
    uint32_t a;
    asm("{ .reg .u64 t; cvta.to.shared.u64 t, %1; cvt.u32.u64 %0, t; }"
        : "=r"(a) : "l"(p));
    return a;
}

// ---------------------------------------------------------------------------
// Projection y0 = x[i,:] . w  (warp per node) + deg init (self-loop = 1).
// ---------------------------------------------------------------------------
__global__ void k_proj(const float* __restrict__ x,
                       const float* __restrict__ W) {
    int warp = (blockIdx.x * blockDim.x + threadIdx.x) >> 5;
    int lane = threadIdx.x & 31;
    if (warp >= N_NODES) return;
    const float* xr = x + (size_t)warp * N_FEATS;
    float s = xr[lane] * __ldg(W + lane) + xr[lane + 32] * __ldg(W + lane + 32);
    #pragma unroll
    for (int off = 16; off > 0; off >>= 1)
        s += __shfl_xor_sync(0xFFFFFFFFu, s, off);
    if (lane == 0) {
        g_a[warp]   = s;
        g_deg[warp] = 1.0f;
    }
}

// ---------------------------------------------------------------------------
// Degree at destination + index packing (4 edges/thread).
// ---------------------------------------------------------------------------
__global__ void __launch_bounds__(256)
k_degpack(const int* __restrict__ row, const int* __restrict__ col) {
    int t = blockIdx.x * blockDim.x + threadIdx.x;
    if (t >= NQUADS) return;
    int4 r = reinterpret_cast<const int4*>(row)[t];
    int4 c = reinterpret_cast<const int4*>(col)[t];
    uint4 p;
    p.x = ((unsigned)r.x << 16) | (unsigned)c.x;
    p.y = ((unsigned)r.y << 16) | (unsigned)c.y;
    p.z = ((unsigned)r.z << 16) | (unsigned)c.z;
    p.w = ((unsigned)r.w << 16) | (unsigned)c.w;
    reinterpret_cast<uint4*>(g_packed)[t] = p;
    atomicAdd(&g_deg[c.x], 1.0f);
    atomicAdd(&g_deg[c.y], 1.0f);
    atomicAdd(&g_deg[c.z], 1.0f);
    atomicAdd(&g_deg[c.w], 1.0f);
}

// ---------------------------------------------------------------------------
// u0 = rsqrt(deg) * y0 -> gather-source + accumulator (self-loop term).
// ---------------------------------------------------------------------------
__global__ void k_scale2() {
    int i = blockIdx.x * blockDim.x + threadIdx.x;
    if (i >= N_NODES) return;
    float v = rsqrtf(g_deg[i]) * g_a[i];
    g_b[i] = v;
    g_c[i] = v;
}

// ---------------------------------------------------------------------------
// Mid-hop: u' = s/deg -> next gather-source + accumulator.
// ---------------------------------------------------------------------------
__global__ void k_div2(const float* __restrict__ s,
                       float* __restrict__ u, float* __restrict__ s2) {
    int i = blockIdx.x * blockDim.x + threadIdx.x;
    if (i >= N_NODES) return;
    float v = s[i] / g_deg[i];
    u[i]  = v;
    s2[i] = v;
}

// ---------------------------------------------------------------------------
// Final: out = rsqrt(deg) * s3 + b.
// ---------------------------------------------------------------------------
__global__ void k_final(float* __restrict__ out, const float* __restrict__ b) {
    int i = blockIdx.x * blockDim.x + threadIdx.x;
    if (i >= N_NODES) return;
    out[i] = rsqrtf(g_deg[i]) * out[i] + __ldg(b);
}

// ---------------------------------------------------------------------------
// Staged edge pass: TMA-bulk-copy the full src vector (195KB) into SMEM,
// then dst[col] += smem_src[row] for this block's edge share.
// Gathers become LDS (bank-conflict cost ~4-6 cyc/warp instead of the ~66 cyc
// L1tex-wavefront cost of a 32-way-divergent LDG). REDs stay global.
// ---------------------------------------------------------------------------
__global__ void __launch_bounds__(1024, 1)
k_edge_staged(const float* __restrict__ src, float* __restrict__ dst) {
    extern __shared__ __align__(16) unsigned char smem_raw[];
    float* s_src = reinterpret_cast<float*>(smem_raw + 16);
    uint32_t mbar  = smem_u32(smem_raw);
    uint32_t sdata = mbar + 16;

    if (threadIdx.x == 0) {
        asm volatile("mbarrier.init.shared.b64 [%0], %1;"
                     :: "r"(mbar), "r"(1u) : "memory");
    }
    __syncthreads();
    if (threadIdx.x == 0) {
        asm volatile("mbarrier.arrive.expect_tx.shared.b64 _, [%0], %1;"
                     :: "r"(mbar), "r"((unsigned)SRC_BYTES) : "memory");
        #pragma unroll
        for (int c = 0; c < 4; c++) {   // 4 chunks of 50000 B (mult of 16)
            asm volatile(
                "cp.async.bulk.shared::cta.global.mbarrier::complete_tx::bytes "
                "[%0], [%1], %2, [%3];"
                :: "r"(sdata + c * (SRC_BYTES / 4)),
                   "l"(src + (size_t)c * (N_NODES / 4)),
                   "r"((unsigned)(SRC_BYTES / 4)),
                   "r"(mbar)
                : "memory");
        }
    }
    // Wait for TMA completion (acquire orders subsequent LDS reads).
    {
        uint32_t done;
        asm volatile(
            "{\n\t.reg .pred p;\n\t"
            "mbarrier.try_wait.parity.acquire.cta.shared::cta.b64 p, [%1], %2;\n\t"
            "selp.b32 %0, 1, 0, p;\n\t}"
            : "=r"(done) : "r"(mbar), "r"(0u) : "memory");
        if (!done) {
            asm volatile(
                "{\n\t.reg .pred P1;\n\t"
                "WL_%=:\n\t"
                "mbarrier.try_wait.parity.acquire.cta.shared::cta.b64 P1, [%0], %1, 0x989680;\n\t"
                "@P1 bra.uni WD_%=;\n\t"
                "bra.uni WL_%=;\n\t"
                "WD_%=:\n\t}"
                :: "r"(mbar), "r"(0u) : "memory");
        }
    }

    int stride = gridDim.x * blockDim.x;
    for (int t = blockIdx.x * blockDim.x + threadIdx.x; t < NQUADS; t += stride) {
        uint4 p = reinterpret_cast<const uint4*>(g_packed)[t];
        float v0 = s_src[p.x >> 16];
        float v1 = s_src[p.y >> 16];
        float v2 = s_src[p.z >> 16];
        float v3 = s_src[p.w >> 16];
        atomicAdd(dst + (p.x & 0xFFFFu), v0);
        atomicAdd(dst + (p.y & 0xFFFFu), v1);
        atomicAdd(dst + (p.z & 0xFFFFu), v2);
        atomicAdd(dst + (p.w & 0xFFFFu), v3);
    }
}

extern "C" void kernel_launch(void* const* d_in, const int* in_sizes, int n_in,
                              void* d_out, int out_size) {
    const float* x  = (const float*)d_in[0];
    const int*   ei = (const int*)d_in[1];   // [2, N_EDGES]
    const float* W  = (const float*)d_in[2]; // [1, N_FEATS]
    const float* b  = (const float*)d_in[3]; // [1]
    float* out = (float*)d_out;              // [N_NODES, 1]

    const int* row = ei;
    const int* col = ei + N_EDGES;

    float* ap; cudaGetSymbolAddress((void**)&ap, g_a);
    float* bp; cudaGetSymbolAddress((void**)&bp, g_b);
    float* cp; cudaGetSymbolAddress((void**)&cp, g_c);

    static bool attr_set = false;
    if (!attr_set) {
        cudaFuncSetAttribute(k_edge_staged,
                             cudaFuncAttributeMaxDynamicSharedMemorySize,
                             SMEM_TOTAL);
        attr_set = true;
    }

    const int TB = 256;
    int grid_nodes = (N_NODES + TB - 1) / TB;
    int grid_proj  = (N_NODES * 32 + TB - 1) / TB;
    int grid_quads = (NQUADS + TB - 1) / TB;
    int grid_edge  = 152;   // one 195KB-smem block per SM (GB300: 152 SMs)

    k_proj<<<grid_proj, TB>>>(x, W);
    k_degpack<<<grid_quads, TB>>>(row, col);

    // hop 1
    k_scale2<<<grid_nodes, TB>>>();
    k_edge_staged<<<grid_edge, 1024, SMEM_TOTAL>>>(bp, cp);

    // hop 2
    k_div2<<<grid_nodes, TB>>>(cp, ap, bp);
    k_edge_staged<<<grid_edge, 1024, SMEM_TOTAL>>>(ap, bp);

    // hop 3 (accumulate into d_out)
    k_div2<<<grid_nodes, TB>>>(bp, cp, out);
    k_edge_staged<<<grid_edge, 1024, SMEM_TOTAL>>>(cp, out);

    k_final<<<grid_nodes, TB>>>(out, b);
}